// round 4
// baseline (speedup 1.0000x reference)
#include <cuda_runtime.h>
#include <cuda_bf16.h>
#include <cstdint>

// Problem dims (fixed)
#define NN   8192
#define D0   128
#define D1   256
#define D2   256
#define QH   128
#define EPSV 1e-5f

// bigmm tiling: BM=64, BN=256 (full), BK=64, 2-stage
#define BM       64
#define BKK      64
#define NIT      (NN / BKK)          // 128
#define PITCH    144                 // 128B data + 16B pad (conflict-free ldsm)
#define SA_SZ    (64 * PITCH)        // 9216  (one A matrix tile)
#define SB_SZ    (256 * PITCH)       // 36864 (one B matrix tile)
#define STAGE_SZ (2 * SA_SZ + 2 * SB_SZ)   // 92160
#define DSMEM_MM (2 * STAGE_SZ)            // 184320

// ---------------- scratch ---------------------------------------------------
__device__ float g_h[NN * D1];
__device__ float g_h2[NN * D2];
__device__ float g_part[64 * 2 * D0];
__device__ float g_mean[D0];
__device__ float g_rstd[D0];
__device__ __nv_bfloat16 g_Bhi[(size_t)D1 * NN];
__device__ __nv_bfloat16 g_Blo[(size_t)D1 * NN];
__device__ __nv_bfloat16 g_B2hi[(size_t)D2 * NN];
__device__ __nv_bfloat16 g_B2lo[(size_t)D2 * NN];

// ---------------- PTX helpers (baseline ISA) --------------------------------
__device__ __forceinline__ uint32_t smem_u32(const void* p) {
    uint32_t a;
    asm("{ .reg .u64 t; cvta.to.shared.u64 t, %1; cvt.u32.u64 %0, t; }" : "=r"(a) : "l"(p));
    return a;
}
__device__ __forceinline__ void cp_async16(uint32_t dst, const void* src) {
    asm volatile("cp.async.cg.shared.global [%0], [%1], 16;" :: "r"(dst), "l"(src) : "memory");
}
__device__ __forceinline__ void ldsm4(uint32_t& r0, uint32_t& r1, uint32_t& r2, uint32_t& r3,
                                      uint32_t a) {
    asm volatile("ldmatrix.sync.aligned.m8n8.x4.shared.b16 {%0,%1,%2,%3}, [%4];"
                 : "=r"(r0), "=r"(r1), "=r"(r2), "=r"(r3) : "r"(a));
}
__device__ __forceinline__ void mma_bf16(float* c, const uint32_t* a, const uint32_t* b) {
    asm volatile("mma.sync.aligned.m16n8k16.row.col.f32.bf16.bf16.f32 "
                 "{%0,%1,%2,%3}, {%4,%5,%6,%7}, {%8,%9}, {%0,%1,%2,%3};"
                 : "+f"(c[0]), "+f"(c[1]), "+f"(c[2]), "+f"(c[3])
                 : "r"(a[0]), "r"(a[1]), "r"(a[2]), "r"(a[3]), "r"(b[0]), "r"(b[1]));
}
__device__ __forceinline__ uint32_t pack_bf16x2(__nv_bfloat16 a, __nv_bfloat16 b) {
    uint16_t ua = *(uint16_t*)&a, ub = *(uint16_t*)&b;
    return (uint32_t)ua | ((uint32_t)ub << 16);
}

// ---------------- batchnorm stats -------------------------------------------
__global__ void bn_partial_kernel(const float* __restrict__ state) {
    int c = threadIdx.x, b = blockIdx.x;
    int r0 = b * (NN / 64);
    float s = 0.f, s2 = 0.f;
    #pragma unroll 4
    for (int r = 0; r < NN / 64; ++r) {
        float v = state[(size_t)(r0 + r) * D0 + c];
        s += v; s2 += v * v;
    }
    g_part[b * 2 * D0 + c]      = s;
    g_part[b * 2 * D0 + D0 + c] = s2;
}
__global__ void bn_final_kernel() {
    int c = threadIdx.x;
    float s = 0.f, s2 = 0.f;
    #pragma unroll
    for (int b = 0; b < 64; ++b) {
        s  += g_part[b * 2 * D0 + c];
        s2 += g_part[b * 2 * D0 + D0 + c];
    }
    float mean = s * (1.0f / NN);
    float var  = s2 * (1.0f / NN) - mean * mean;
    g_mean[c] = mean;
    g_rstd[c] = rsqrtf(var + EPSV);
}

// ---------------- fused row-block MLP: out^T split bf16 ----------------------
// Computes, for a 64-row slab: Y = src[64,K] @ W[K,256], then writes
// outHi/outLo[c][m0+r] = bf16 split of Y[r][c].  Optional fused batchnorm on src.
// Thread (r,q): r=tid>>2, q=tid&3; owns cols {8q+32s+j : s<8, j<8}.
template<int K, bool DOBN>
__global__ void __launch_bounds__(256, 1)
mlpT_kernel(const float* __restrict__ src, const float* __restrict__ W,
            const float* __restrict__ gamma, const float* __restrict__ beta,
            __nv_bfloat16* __restrict__ outHi, __nv_bfloat16* __restrict__ outLo) {
    constexpr int PX = K + 4;
    extern __shared__ char smr[];
    float* xs = (float*)smr;                                   // [64][PX]
    float* ws = (float*)(smr + 64 * PX * 4);                   // [32][256]
    uint32_t* ts = (uint32_t*)(smr + 64 * PX * 4 + 32 * 256 * 4);  // [256][64]
    const int tid = threadIdx.x;
    const int m0 = blockIdx.x * 64;

    // stage slab (optionally batchnormed)
    #pragma unroll
    for (int i = 0; i < K / 4; ++i) {
        int id = i * 256 + tid;
        int r = id / K, c = id % K;
        float v = src[(size_t)(m0 + r) * K + c];
        if (DOBN) v = (v - g_mean[c]) * g_rstd[c] * gamma[c] + beta[c];
        xs[r * PX + c] = v;
    }

    const int r = tid >> 2, q = tid & 3;
    float acc[64];
    #pragma unroll
    for (int i = 0; i < 64; ++i) acc[i] = 0.f;

    for (int kc = 0; kc < K / 32; ++kc) {
        __syncthreads();
        #pragma unroll
        for (int i = 0; i < 32; ++i) {
            int id = i * 256 + tid;
            int kr = id >> 8, c = id & 255;
            ws[kr * 256 + c] = W[(size_t)(kc * 32 + kr) * 256 + c];
        }
        __syncthreads();
        #pragma unroll 4
        for (int k = 0; k < 32; ++k) {
            float a = xs[r * PX + kc * 32 + k];
            const float* wrow = ws + k * 256 + 8 * q;
            #pragma unroll
            for (int s = 0; s < 8; ++s) {
                float4 w0 = *(const float4*)(wrow + 32 * s);
                float4 w1 = *(const float4*)(wrow + 32 * s + 4);
                acc[8 * s + 0] = fmaf(a, w0.x, acc[8 * s + 0]);
                acc[8 * s + 1] = fmaf(a, w0.y, acc[8 * s + 1]);
                acc[8 * s + 2] = fmaf(a, w0.z, acc[8 * s + 2]);
                acc[8 * s + 3] = fmaf(a, w0.w, acc[8 * s + 3]);
                acc[8 * s + 4] = fmaf(a, w1.x, acc[8 * s + 4]);
                acc[8 * s + 5] = fmaf(a, w1.y, acc[8 * s + 5]);
                acc[8 * s + 6] = fmaf(a, w1.z, acc[8 * s + 6]);
                acc[8 * s + 7] = fmaf(a, w1.w, acc[8 * s + 7]);
            }
        }
    }

    // split + transpose through smem (hi in low 16, lo in high 16)
    #pragma unroll
    for (int s = 0; s < 8; ++s)
        #pragma unroll
        for (int j = 0; j < 8; ++j) {
            int c = 8 * q + 32 * s + j;
            float v = acc[8 * s + j];
            __nv_bfloat16 hi = __float2bfloat16(v);
            __nv_bfloat16 lo = __float2bfloat16(v - __bfloat162float(hi));
            ts[c * 64 + r] = pack_bf16x2(hi, lo);
        }
    __syncthreads();
    // coalesced store: pairs along r
    #pragma unroll
    for (int i = 0; i < 32; ++i) {
        int id = i * 256 + tid;
        int c = id >> 5, rp = (id & 31) * 2;
        uint32_t v0 = ts[c * 64 + rp], v1 = ts[c * 64 + rp + 1];
        uint16_t h0 = v0 & 0xFFFF, l0 = v0 >> 16;
        uint16_t h1 = v1 & 0xFFFF, l1 = v1 >> 16;
        uint32_t hh = (uint32_t)h0 | ((uint32_t)h1 << 16);
        uint32_t ll = (uint32_t)l0 | ((uint32_t)l1 << 16);
        *(uint32_t*)(outHi + (size_t)c * NN + m0 + rp) = hh;
        *(uint32_t*)(outLo + (size_t)c * NN + m0 + rp) = ll;
    }
}

// ---------------- fused Q head: out = relu(h2@Wq1+bq1)@Wq2 + bq2 -------------
__global__ void __launch_bounds__(256, 1)
qhead_kernel(const float* __restrict__ h2, const float* __restrict__ Wq1,
             const float* __restrict__ bq1, const float* __restrict__ Wq2,
             const float* __restrict__ bq2, float* __restrict__ out) {
    constexpr int K = 256, PX = K + 4;
    extern __shared__ char smr[];
    float* xs = (float*)smr;                     // [64][260]
    float* ws = (float*)(smr + 64 * PX * 4);     // [32][128]
    const int tid = threadIdx.x;
    const int m0 = blockIdx.x * 64;

    #pragma unroll
    for (int i = 0; i < 64; ++i) {
        int id = i * 256 + tid;
        int r = id >> 8, c = id & 255;
        xs[r * PX + c] = h2[(size_t)(m0 + r) * K + c];
    }

    const int r = tid >> 2, q = tid & 3;
    float acc[32];
    #pragma unroll
    for (int i = 0; i < 32; ++i) acc[i] = 0.f;

    for (int kc = 0; kc < 8; ++kc) {
        __syncthreads();
        #pragma unroll
        for (int i = 0; i < 16; ++i) {
            int id = i * 256 + tid;
            int kr = id >> 7, c = id & 127;
            ws[kr * 128 + c] = Wq1[(size_t)(kc * 32 + kr) * 128 + c];
        }
        __syncthreads();
        #pragma unroll 4
        for (int k = 0; k < 32; ++k) {
            float a = xs[r * PX + kc * 32 + k];
            const float* wrow = ws + k * 128 + 8 * q;
            #pragma unroll
            for (int s = 0; s < 4; ++s) {
                float4 w0 = *(const float4*)(wrow + 32 * s);
                float4 w1 = *(const float4*)(wrow + 32 * s + 4);
                acc[8 * s + 0] = fmaf(a, w0.x, acc[8 * s + 0]);
                acc[8 * s + 1] = fmaf(a, w0.y, acc[8 * s + 1]);
                acc[8 * s + 2] = fmaf(a, w0.z, acc[8 * s + 2]);
                acc[8 * s + 3] = fmaf(a, w0.w, acc[8 * s + 3]);
                acc[8 * s + 4] = fmaf(a, w1.x, acc[8 * s + 4]);
                acc[8 * s + 5] = fmaf(a, w1.y, acc[8 * s + 5]);
                acc[8 * s + 6] = fmaf(a, w1.z, acc[8 * s + 6]);
                acc[8 * s + 7] = fmaf(a, w1.w, acc[8 * s + 7]);
            }
        }
    }

    float part = 0.f;
    #pragma unroll
    for (int s = 0; s < 4; ++s)
        #pragma unroll
        for (int j = 0; j < 8; ++j) {
            int c = 8 * q + 32 * s + j;
            float t = fmaxf(acc[8 * s + j] + bq1[c], 0.f);
            part += t * Wq2[c];
        }
    part += __shfl_xor_sync(0xffffffffu, part, 1);
    part += __shfl_xor_sync(0xffffffffu, part, 2);
    if (q == 0) out[m0 + r] = part + bq2[0];
}

// ---------------- big GEMM: C = relu(A_fp32 @ B^T + bias) --------------------
// A fp32 [NN,NN], split to bf16 hi/lo in-kernel.  B hi/lo [256,NN] bf16.
// Tile 64x256xK64, 8 warps, 2-stage pipeline (cp.async for B, LDG+cvt+STS for A).
__global__ void __launch_bounds__(256, 1)
bigmm_kernel(const float* __restrict__ A,
             const __nv_bfloat16* __restrict__ Bhi, const __nv_bfloat16* __restrict__ Blo,
             const float* __restrict__ bias, float* __restrict__ C) {
    extern __shared__ char sm[];
    const uint32_t sbase = smem_u32(sm);
    const int tid = threadIdx.x;
    const int m0 = blockIdx.x * BM;
    const int lrow = tid >> 2, lchk = tid & 3;

    const float* gA = A + (size_t)(m0 + lrow) * NN + lchk * 16;
    const __nv_bfloat16* gBh = Bhi + (size_t)lrow * NN + lchk * 16;
    const __nv_bfloat16* gBl = Blo + (size_t)lrow * NN + lchk * 16;
    const uint32_t sAoff = (uint32_t)lrow * PITCH + lchk * 32;

    float4 rA[4];
    auto LDG_A = [&](int j) {
        const float* p = gA + (size_t)j * BKK;
        rA[0] = *(const float4*)(p + 0);
        rA[1] = *(const float4*)(p + 4);
        rA[2] = *(const float4*)(p + 8);
        rA[3] = *(const float4*)(p + 12);
    };
    auto STS_A = [&](int s) {
        const float* f = (const float*)rA;
        uint32_t hbuf[8], lbuf[8];
        #pragma unroll
        for (int e = 0; e < 8; ++e) {
            float x0 = f[2 * e], x1 = f[2 * e + 1];
            __nv_bfloat16 h0 = __float2bfloat16(x0);
            __nv_bfloat16 h1 = __float2bfloat16(x1);
            __nv_bfloat16 l0 = __float2bfloat16(x0 - __bfloat162float(h0));
            __nv_bfloat16 l1 = __float2bfloat16(x1 - __bfloat162float(h1));
            hbuf[e] = pack_bf16x2(h0, h1);
            lbuf[e] = pack_bf16x2(l0, l1);
        }
        char* dh = sm + s * STAGE_SZ + sAoff;
        char* dl = dh + SA_SZ;
        *(uint4*)(dh)      = *(uint4*)&hbuf[0];
        *(uint4*)(dh + 16) = *(uint4*)&hbuf[4];
        *(uint4*)(dl)      = *(uint4*)&lbuf[0];
        *(uint4*)(dl + 16) = *(uint4*)&lbuf[4];
    };
    auto CP_B = [&](int s, int j) {
        uint32_t sb = sbase + s * STAGE_SZ + 2 * SA_SZ;
        size_t k = (size_t)j * BKK;
        #pragma unroll
        for (int i2 = 0; i2 < 4; ++i2) {
            uint32_t d = sb + (uint32_t)(lrow + 64 * i2) * PITCH + lchk * 32;
            const __nv_bfloat16* ph = gBh + k + (size_t)(64 * i2) * NN;
            const __nv_bfloat16* pl = gBl + k + (size_t)(64 * i2) * NN;
            cp_async16(d,             ph);
            cp_async16(d + 16,        ph + 8);
            cp_async16(d + SB_SZ,      pl);
            cp_async16(d + SB_SZ + 16, pl + 8);
        }
        asm volatile("cp.async.commit_group;" ::: "memory");
    };

    // compute mapping
    const int wid = tid >> 5, lane = tid & 31;
    const int wm = wid & 1, wn = wid >> 1;
    const uint32_t aLane = (uint32_t)(wm * 32 + (lane & 15)) * PITCH + (lane >> 4) * 16;
    const uint32_t bLane = (uint32_t)(wn * 64 + ((lane >> 4) << 3) + (lane & 7)) * PITCH
                           + ((lane >> 3) & 1) * 16;

    float acc[2][8][4];
    #pragma unroll
    for (int mt = 0; mt < 2; ++mt)
        #pragma unroll
        for (int nt = 0; nt < 8; ++nt)
            #pragma unroll
            for (int e = 0; e < 4; ++e) acc[mt][nt][e] = 0.f;

    // prologue
    LDG_A(0);
    STS_A(0);
    CP_B(0, 0);
    LDG_A(1);

    for (int j = 0; j < NIT; ++j) {
        asm volatile("cp.async.wait_group 0;" ::: "memory");
        __syncthreads();
        const int s = j & 1;
        if (j + 1 < NIT) {
            CP_B((j + 1) & 1, j + 1);
            STS_A((j + 1) & 1);
        }
        if (j + 2 < NIT) LDG_A(j + 2);

        const uint32_t sb = sbase + s * STAGE_SZ;
        #pragma unroll
        for (int kh = 0; kh < 4; ++kh) {
            uint32_t ah[2][4], al[2][4], bh[8][2], bl[8][2];
            #pragma unroll
            for (int mt = 0; mt < 2; ++mt) {
                uint32_t ad = sb + aLane + mt * (16 * PITCH) + kh * 32;
                ldsm4(ah[mt][0], ah[mt][1], ah[mt][2], ah[mt][3], ad);
                ldsm4(al[mt][0], al[mt][1], al[mt][2], al[mt][3], ad + SA_SZ);
            }
            #pragma unroll
            for (int p = 0; p < 4; ++p) {
                uint32_t bd = sb + 2 * SA_SZ + bLane + p * (16 * PITCH) + kh * 32;
                uint32_t r0, r1, r2, r3;
                ldsm4(r0, r1, r2, r3, bd);
                bh[2 * p][0] = r0; bh[2 * p][1] = r1;
                bh[2 * p + 1][0] = r2; bh[2 * p + 1][1] = r3;
                ldsm4(r0, r1, r2, r3, bd + SB_SZ);
                bl[2 * p][0] = r0; bl[2 * p][1] = r1;
                bl[2 * p + 1][0] = r2; bl[2 * p + 1][1] = r3;
            }
            #pragma unroll
            for (int mt = 0; mt < 2; ++mt)
                #pragma unroll
                for (int nt = 0; nt < 8; ++nt)
                    mma_bf16(acc[mt][nt], ah[mt], bh[nt]);
            #pragma unroll
            for (int mt = 0; mt < 2; ++mt)
                #pragma unroll
                for (int nt = 0; nt < 8; ++nt)
                    mma_bf16(acc[mt][nt], ah[mt], bl[nt]);
            #pragma unroll
            for (int mt = 0; mt < 2; ++mt)
                #pragma unroll
                for (int nt = 0; nt < 8; ++nt)
                    mma_bf16(acc[mt][nt], al[mt], bh[nt]);
        }
    }

    // epilogue: bias + relu + store
    #pragma unroll
    for (int mt = 0; mt < 2; ++mt) {
        #pragma unroll
        for (int nt = 0; nt < 8; ++nt) {
            int r = m0 + wm * 32 + mt * 16 + (lane >> 2);
            int c = wn * 64 + nt * 8 + (lane & 3) * 2;
            float b0 = bias[c], b1 = bias[c + 1];
            float2 v0;
            v0.x = fmaxf(acc[mt][nt][0] + b0, 0.f);
            v0.y = fmaxf(acc[mt][nt][1] + b1, 0.f);
            *(float2*)(C + (size_t)r * 256 + c) = v0;
            float2 v1;
            v1.x = fmaxf(acc[mt][nt][2] + b0, 0.f);
            v1.y = fmaxf(acc[mt][nt][3] + b1, 0.f);
            *(float2*)(C + (size_t)(r + 8) * 256 + c) = v1;
        }
    }
}

// ---------------- launcher --------------------------------------------------
extern "C" void kernel_launch(void* const* d_in, const int* in_sizes, int n_in,
                              void* d_out, int out_size) {
    const float* state = (const float*)d_in[0];
    const float* adj   = (const float*)d_in[1];
    const float* gamma = (const float*)d_in[2];
    const float* beta  = (const float*)d_in[3];
    const float* W1    = (const float*)d_in[4];
    const float* b1    = (const float*)d_in[5];
    const float* W2    = (const float*)d_in[6];
    const float* b2    = (const float*)d_in[7];
    const float* Wq1   = (const float*)d_in[8];
    const float* bq1   = (const float*)d_in[9];
    const float* Wq2   = (const float*)d_in[10];
    const float* bq2   = (const float*)d_in[11];
    float* out = (float*)d_out;

    float *gh, *gh2;
    __nv_bfloat16 *gBhi, *gBlo, *gB2hi, *gB2lo;
    cudaGetSymbolAddress((void**)&gh, g_h);
    cudaGetSymbolAddress((void**)&gh2, g_h2);
    cudaGetSymbolAddress((void**)&gBhi, g_Bhi);
    cudaGetSymbolAddress((void**)&gBlo, g_Blo);
    cudaGetSymbolAddress((void**)&gB2hi, g_B2hi);
    cudaGetSymbolAddress((void**)&gB2lo, g_B2lo);

    const int SM_XW1 = 64 * 132 * 4 + 32 * 256 * 4 + 256 * 64 * 4;  // 132096
    const int SM_HW2 = 64 * 260 * 4 + 32 * 256 * 4 + 256 * 64 * 4;  // 164864
    const int SM_QH  = 64 * 260 * 4 + 32 * 128 * 4;                 // 82944
    cudaFuncSetAttribute(bigmm_kernel, cudaFuncAttributeMaxDynamicSharedMemorySize, DSMEM_MM);
    cudaFuncSetAttribute(mlpT_kernel<128, true>, cudaFuncAttributeMaxDynamicSharedMemorySize, SM_XW1);
    cudaFuncSetAttribute(mlpT_kernel<256, false>, cudaFuncAttributeMaxDynamicSharedMemorySize, SM_HW2);
    cudaFuncSetAttribute(qhead_kernel, cudaFuncAttributeMaxDynamicSharedMemorySize, SM_QH);

    // BatchNorm stats
    bn_partial_kernel<<<64, D0>>>(state);
    bn_final_kernel<<<1, D0>>>();

    // Y1^T = (bn(state) @ W1)^T, split bf16
    mlpT_kernel<128, true><<<NN / 64, 256, SM_XW1>>>(state, W1, gamma, beta, gBhi, gBlo);

    // h1 = relu(A @ Y1 + b1)
    bigmm_kernel<<<NN / BM, 256, DSMEM_MM>>>(adj, gBhi, gBlo, b1, gh);

    // Y2^T = (h1 @ W2)^T, split bf16
    mlpT_kernel<256, false><<<NN / 64, 256, SM_HW2>>>(gh, W2, nullptr, nullptr, gB2hi, gB2lo);

    // h2 = relu(A @ Y2 + b2)
    bigmm_kernel<<<NN / BM, 256, DSMEM_MM>>>(adj, gB2hi, gB2lo, b2, gh2);

    // q = relu(h2 @ Wq1 + bq1) @ Wq2 + bq2
    qhead_kernel<<<NN / 64, 256, SM_QH>>>(gh2, Wq1, bq1, Wq2, bq2, out);
}

// round 5
// speedup vs baseline: 1.6086x; 1.6086x over previous
#include <cuda_runtime.h>
#include <cuda_bf16.h>
#include <cstdint>

// Problem dims (fixed)
#define NN   8192
#define D0   128
#define D1   256
#define D2   256
#define QH   128
#define EPSV 1e-5f

// bigmm tiling: BM=64, BN=128, BK=32, 3 stages, 2 CTAs/SM
#define BM       64
#define BNT      128
#define BKK      32
#define NIT      (NN / BKK)              // 256
#define PITCH    80                      // 64B data + 16B pad per 32-elem bf16 row
#define SA_SZ    (64 * PITCH)            // 5120  per A matrix (hi or lo)
#define SB_SZ    (BNT * PITCH)           // 10240 per B matrix (hi or lo)
#define STAGE_SZ (2 * SA_SZ + 2 * SB_SZ) // 30720
#define NSTAGE   3
#define DSMEM_MM (NSTAGE * STAGE_SZ)     // 92160 -> 2 CTAs/SM

// ---------------- scratch ---------------------------------------------------
__device__ float g_x[NN * D0];           // bn(state); later Q-hidden [NN,128]
__device__ float g_y[NN * D1];           // XW products
__device__ float g_h[NN * D2];           // hidden (reused for h1 then h2)
__device__ float g_part[64 * 2 * D0];
__device__ float g_mean[D0];
__device__ float g_rstd[D0];
__device__ __nv_bfloat16 g_Bhi[(size_t)D1 * NN];   // Y^T hi [256, 8192]
__device__ __nv_bfloat16 g_Blo[(size_t)D1 * NN];   // Y^T lo

// ---------------- PTX helpers (baseline ISA) --------------------------------
__device__ __forceinline__ uint32_t smem_u32(const void* p) {
    uint32_t a;
    asm("{ .reg .u64 t; cvta.to.shared.u64 t, %1; cvt.u32.u64 %0, t; }" : "=r"(a) : "l"(p));
    return a;
}
__device__ __forceinline__ void cp_async16(uint32_t dst, const void* src) {
    asm volatile("cp.async.cg.shared.global [%0], [%1], 16;" :: "r"(dst), "l"(src) : "memory");
}
__device__ __forceinline__ void ldsm4(uint32_t& r0, uint32_t& r1, uint32_t& r2, uint32_t& r3,
                                      uint32_t a) {
    asm volatile("ldmatrix.sync.aligned.m8n8.x4.shared.b16 {%0,%1,%2,%3}, [%4];"
                 : "=r"(r0), "=r"(r1), "=r"(r2), "=r"(r3) : "r"(a));
}
__device__ __forceinline__ void mma_bf16(float* c, const uint32_t* a, const uint32_t* b) {
    asm volatile("mma.sync.aligned.m16n8k16.row.col.f32.bf16.bf16.f32 "
                 "{%0,%1,%2,%3}, {%4,%5,%6,%7}, {%8,%9}, {%0,%1,%2,%3};"
                 : "+f"(c[0]), "+f"(c[1]), "+f"(c[2]), "+f"(c[3])
                 : "r"(a[0]), "r"(a[1]), "r"(a[2]), "r"(a[3]), "r"(b[0]), "r"(b[1]));
}
__device__ __forceinline__ uint32_t pack_bf16x2(__nv_bfloat16 a, __nv_bfloat16 b) {
    uint16_t ua = *(uint16_t*)&a, ub = *(uint16_t*)&b;
    return (uint32_t)ua | ((uint32_t)ub << 16);
}

// ---------------- batchnorm ------------------------------------------------
__global__ void bn_partial_kernel(const float* __restrict__ state) {
    int c = threadIdx.x, b = blockIdx.x;
    int r0 = b * (NN / 64);
    float s = 0.f, s2 = 0.f;
    #pragma unroll 4
    for (int r = 0; r < NN / 64; ++r) {
        float v = state[(size_t)(r0 + r) * D0 + c];
        s += v; s2 += v * v;
    }
    g_part[b * 2 * D0 + c]      = s;
    g_part[b * 2 * D0 + D0 + c] = s2;
}
__global__ void bn_final_kernel() {
    int c = threadIdx.x;
    float s = 0.f, s2 = 0.f;
    #pragma unroll
    for (int b = 0; b < 64; ++b) {
        s  += g_part[b * 2 * D0 + c];
        s2 += g_part[b * 2 * D0 + D0 + c];
    }
    float mean = s * (1.0f / NN);
    float var  = s2 * (1.0f / NN) - mean * mean;
    g_mean[c] = mean;
    g_rstd[c] = rsqrtf(var + EPSV);
}
__global__ void bn_apply_kernel(const float* __restrict__ state,
                                const float* __restrict__ gamma,
                                const float* __restrict__ beta) {
    int i = blockIdx.x * blockDim.x + threadIdx.x;
    int c = i & (D0 - 1);
    float v = state[i];
    g_x[i] = (v - g_mean[c]) * g_rstd[c] * gamma[c] + beta[c];
}

// ---------------- Y [NN,256] fp32 -> transposed bf16 hi/lo [256, NN] --------
__global__ void convT_kernel(const float* __restrict__ Y) {
    __shared__ float tile[32][33];
    int n0 = blockIdx.x * 32;
    int c0 = blockIdx.y * 32;
    int tx = threadIdx.x, ty = threadIdx.y;   // 32 x 8
    #pragma unroll
    for (int r = 0; r < 32; r += 8)
        tile[ty + r][tx] = Y[(size_t)(n0 + ty + r) * 256 + c0 + tx];
    __syncthreads();
    #pragma unroll
    for (int r = 0; r < 32; r += 8) {
        float v = tile[tx][ty + r];
        __nv_bfloat16 hi = __float2bfloat16(v);
        __nv_bfloat16 lo = __float2bfloat16(v - __bfloat162float(hi));
        size_t o = (size_t)(c0 + ty + r) * NN + n0 + tx;
        g_Bhi[o] = hi;
        g_Blo[o] = lo;
    }
}

// ---------------- big GEMM: C = relu(A_fp32 @ B^T + bias) --------------------
// A fp32 [NN,NN] row-major, split to bf16 hi/lo in-kernel (LDG->cvt->STS).
// B hi/lo [256,NN] bf16 K-major (cp.async).  Tile 64x128xK32, 8 warps,
// 3-stage pipeline, 2 CTAs/SM.
__global__ void __launch_bounds__(256, 2)
bigmm_kernel(const float* __restrict__ A,
             const __nv_bfloat16* __restrict__ Bhi, const __nv_bfloat16* __restrict__ Blo,
             const float* __restrict__ bias, float* __restrict__ C) {
    extern __shared__ char sm[];
    const uint32_t sbase = smem_u32(sm);
    const int tid = threadIdx.x;
    const int n0 = blockIdx.x * BNT;
    const int m0 = blockIdx.y * BM;
    const int lrow = tid >> 2, lchk = tid & 3;

    // ---- loaders ----
    const float* gA = A + (size_t)(m0 + lrow) * NN + lchk * 8;
    const __nv_bfloat16* gBh = Bhi + (size_t)(n0 + lrow) * NN + lchk * 8;
    const __nv_bfloat16* gBl = Blo + (size_t)(n0 + lrow) * NN + lchk * 8;
    const uint32_t sAoff = (uint32_t)lrow * PITCH + lchk * 16;

    float4 rA[2];
    auto LDG_A = [&](int j) {
        const float* p = gA + (size_t)j * BKK;
        rA[0] = *(const float4*)(p + 0);
        rA[1] = *(const float4*)(p + 4);
    };
    auto STS_A = [&](int s) {
        const float* f = (const float*)rA;
        uint32_t hbuf[4], lbuf[4];
        #pragma unroll
        for (int e = 0; e < 4; ++e) {
            float x0 = f[2 * e], x1 = f[2 * e + 1];
            __nv_bfloat16 h0 = __float2bfloat16(x0);
            __nv_bfloat16 h1 = __float2bfloat16(x1);
            __nv_bfloat16 l0 = __float2bfloat16(x0 - __bfloat162float(h0));
            __nv_bfloat16 l1 = __float2bfloat16(x1 - __bfloat162float(h1));
            hbuf[e] = pack_bf16x2(h0, h1);
            lbuf[e] = pack_bf16x2(l0, l1);
        }
        char* dh = sm + s * STAGE_SZ + sAoff;
        *(uint4*)(dh)         = *(uint4*)hbuf;
        *(uint4*)(dh + SA_SZ) = *(uint4*)lbuf;
    };
    auto CP_B = [&](int s, int j) {
        uint32_t sb = sbase + s * STAGE_SZ + 2 * SA_SZ;
        size_t k = (size_t)j * BKK;
        #pragma unroll
        for (int i2 = 0; i2 < 2; ++i2) {
            uint32_t d = sb + (uint32_t)(lrow + 64 * i2) * PITCH + lchk * 16;
            cp_async16(d,         gBh + k + (size_t)(64 * i2) * NN);
            cp_async16(d + SB_SZ, gBl + k + (size_t)(64 * i2) * NN);
        }
        asm volatile("cp.async.commit_group;" ::: "memory");
    };

    // ---- compute mapping: 8 warps = 2(m) x 4(n), warp tile 32x32 ----
    const int wid = tid >> 5, lane = tid & 31;
    const int wm = wid & 1, wn = wid >> 1;
    const uint32_t aLane = (uint32_t)(wm * 32 + (lane & 15)) * PITCH + (lane >> 4) * 16;
    const uint32_t bLane = (uint32_t)(wn * 32 + ((lane >> 4) << 3) + (lane & 7)) * PITCH
                           + ((lane >> 3) & 1) * 16;

    float acc[2][4][4];
    #pragma unroll
    for (int mt = 0; mt < 2; ++mt)
        #pragma unroll
        for (int nt = 0; nt < 4; ++nt)
            #pragma unroll
            for (int e = 0; e < 4; ++e) acc[mt][nt][e] = 0.f;

    // ---- prologue ----
    LDG_A(0); STS_A(0); CP_B(0, 0);
    LDG_A(1); STS_A(1); CP_B(1, 1);
    LDG_A(2);

    for (int j = 0; j < NIT; ++j) {
        if (j + 2 < NIT) {
            asm volatile("cp.async.wait_group 1;" ::: "memory");
        } else {
            asm volatile("cp.async.wait_group 0;" ::: "memory");
        }
        __syncthreads();
        const int s = j % NSTAGE;
        if (j + 2 < NIT) {
            const int ls = (j + 2) % NSTAGE;
            STS_A(ls);            // rA holds data for iteration j+2
            CP_B(ls, j + 2);
        }
        if (j + 3 < NIT) LDG_A(j + 3);

        const uint32_t sb = sbase + s * STAGE_SZ;
        #pragma unroll
        for (int kh = 0; kh < 2; ++kh) {
            uint32_t ah[2][4], al[2][4], bh[4][2], bl[4][2];
            #pragma unroll
            for (int mt = 0; mt < 2; ++mt) {
                uint32_t ad = sb + aLane + mt * (16 * PITCH) + kh * 32;
                ldsm4(ah[mt][0], ah[mt][1], ah[mt][2], ah[mt][3], ad);
                ldsm4(al[mt][0], al[mt][1], al[mt][2], al[mt][3], ad + SA_SZ);
            }
            #pragma unroll
            for (int p = 0; p < 2; ++p) {
                uint32_t bd = sb + 2 * SA_SZ + bLane + p * (16 * PITCH) + kh * 32;
                uint32_t r0, r1, r2, r3;
                ldsm4(r0, r1, r2, r3, bd);
                bh[2 * p][0] = r0; bh[2 * p][1] = r1;
                bh[2 * p + 1][0] = r2; bh[2 * p + 1][1] = r3;
                ldsm4(r0, r1, r2, r3, bd + SB_SZ);
                bl[2 * p][0] = r0; bl[2 * p][1] = r1;
                bl[2 * p + 1][0] = r2; bl[2 * p + 1][1] = r3;
            }
            #pragma unroll
            for (int mt = 0; mt < 2; ++mt)
                #pragma unroll
                for (int nt = 0; nt < 4; ++nt)
                    mma_bf16(acc[mt][nt], ah[mt], bh[nt]);
            #pragma unroll
            for (int mt = 0; mt < 2; ++mt)
                #pragma unroll
                for (int nt = 0; nt < 4; ++nt)
                    mma_bf16(acc[mt][nt], ah[mt], bl[nt]);
            #pragma unroll
            for (int mt = 0; mt < 2; ++mt)
                #pragma unroll
                for (int nt = 0; nt < 4; ++nt)
                    mma_bf16(acc[mt][nt], al[mt], bh[nt]);
        }
    }

    // ---- epilogue: bias + relu + store ----
    #pragma unroll
    for (int mt = 0; mt < 2; ++mt) {
        #pragma unroll
        for (int nt = 0; nt < 4; ++nt) {
            int r = m0 + wm * 32 + mt * 16 + (lane >> 2);
            int c = n0 + wn * 32 + nt * 8 + (lane & 3) * 2;
            float b0 = bias[c], b1 = bias[c + 1];
            float2 v0;
            v0.x = fmaxf(acc[mt][nt][0] + b0, 0.f);
            v0.y = fmaxf(acc[mt][nt][1] + b1, 0.f);
            *(float2*)(C + (size_t)r * 256 + c) = v0;
            float2 v1;
            v1.x = fmaxf(acc[mt][nt][2] + b0, 0.f);
            v1.y = fmaxf(acc[mt][nt][3] + b1, 0.f);
            *(float2*)(C + (size_t)(r + 8) * 256 + c) = v1;
        }
    }
}

// ---------------- small fp32 SGEMM (fused bias/relu) ------------------------
template<bool BIAS, bool RELU>
__global__ void sgemm_kernel(const float* __restrict__ A,
                             const float* __restrict__ B,
                             const float* __restrict__ bias,
                             float* __restrict__ C,
                             int M, int N, int K) {
    constexpr int TBM = 64, TBN = 64, TBK = 16, TM = 4, TN = 4;
    __shared__ float As[TBK][TBM];
    __shared__ float Bs[TBK][TBN];
    const int tid = threadIdx.x;
    const int tx = tid % (TBN / TN);
    const int ty = tid / (TBN / TN);
    const int rowBase = blockIdx.y * TBM;
    const int colBase = blockIdx.x * TBN;
    const int aRow = tid / (TBK / 4);
    const int aCol = (tid % (TBK / 4)) * 4;
    const int bRow = tid / (TBN / 4);
    const int bCol = (tid % (TBN / 4)) * 4;
    float acc[TM][TN] = {};
    for (int k0 = 0; k0 < K; k0 += TBK) {
        float4 av = *(const float4*)(A + (size_t)(rowBase + aRow) * K + k0 + aCol);
        As[aCol + 0][aRow] = av.x; As[aCol + 1][aRow] = av.y;
        As[aCol + 2][aRow] = av.z; As[aCol + 3][aRow] = av.w;
        float4 bv = *(const float4*)(B + (size_t)(k0 + bRow) * N + colBase + bCol);
        *(float4*)&Bs[bRow][bCol] = bv;
        __syncthreads();
        #pragma unroll
        for (int k = 0; k < TBK; ++k) {
            float4 a4 = *(const float4*)&As[k][ty * TM];
            float4 b4 = *(const float4*)&Bs[k][tx * TN];
            float a[TM] = {a4.x, a4.y, a4.z, a4.w};
            float b[TN] = {b4.x, b4.y, b4.z, b4.w};
            #pragma unroll
            for (int i = 0; i < TM; ++i)
                #pragma unroll
                for (int j = 0; j < TN; ++j)
                    acc[i][j] = fmaf(a[i], b[j], acc[i][j]);
        }
        __syncthreads();
    }
    #pragma unroll
    for (int i = 0; i < TM; ++i) {
        int r = rowBase + ty * TM + i;
        #pragma unroll
        for (int j = 0; j < TN; ++j) {
            int c = colBase + tx * TN + j;
            float v = acc[i][j];
            if (BIAS) v += bias[c];
            if (RELU) v = fmaxf(v, 0.f);
            C[(size_t)r * N + c] = v;
        }
    }
}

// ---------------- final Q output --------------------------------------------
__global__ void qout_kernel(const float* __restrict__ T,
                            const float* __restrict__ Wq2,
                            const float* __restrict__ bq2,
                            float* __restrict__ out) {
    int warp = threadIdx.x >> 5;
    int lane = threadIdx.x & 31;
    int row  = blockIdx.x * 8 + warp;
    const float* t = T + (size_t)row * QH;
    float s = 0.f;
    #pragma unroll
    for (int k = lane; k < QH; k += 32) s += t[k] * Wq2[k];
    #pragma unroll
    for (int o = 16; o; o >>= 1) s += __shfl_xor_sync(0xffffffffu, s, o);
    if (lane == 0) out[row] = s + bq2[0];
}

// ---------------- launcher --------------------------------------------------
extern "C" void kernel_launch(void* const* d_in, const int* in_sizes, int n_in,
                              void* d_out, int out_size) {
    const float* state = (const float*)d_in[0];
    const float* adj   = (const float*)d_in[1];
    const float* gamma = (const float*)d_in[2];
    const float* beta  = (const float*)d_in[3];
    const float* W1    = (const float*)d_in[4];
    const float* b1    = (const float*)d_in[5];
    const float* W2    = (const float*)d_in[6];
    const float* b2    = (const float*)d_in[7];
    const float* Wq1   = (const float*)d_in[8];
    const float* bq1   = (const float*)d_in[9];
    const float* Wq2   = (const float*)d_in[10];
    const float* bq2   = (const float*)d_in[11];
    float* out = (float*)d_out;

    float *gx, *gy, *gh;
    cudaGetSymbolAddress((void**)&gx, g_x);
    cudaGetSymbolAddress((void**)&gy, g_y);
    cudaGetSymbolAddress((void**)&gh, g_h);
    __nv_bfloat16 *gBhi, *gBlo;
    cudaGetSymbolAddress((void**)&gBhi, g_Bhi);
    cudaGetSymbolAddress((void**)&gBlo, g_Blo);

    cudaFuncSetAttribute(bigmm_kernel, cudaFuncAttributeMaxDynamicSharedMemorySize, DSMEM_MM);

    // BatchNorm -> g_x
    bn_partial_kernel<<<64, D0>>>(state);
    bn_final_kernel<<<1, D0>>>();
    bn_apply_kernel<<<(NN * D0) / 256, 256>>>(state, gamma, beta);

    // Y1 = x @ W1, then split+transpose
    sgemm_kernel<false, false><<<dim3(D1 / 64, NN / 64), 256>>>(gx, W1, nullptr, gy, NN, D1, D0);
    convT_kernel<<<dim3(NN / 32, 256 / 32), dim3(32, 8)>>>(gy);

    // h1 = relu(A @ Y1 + b1)
    bigmm_kernel<<<dim3(2, NN / BM), 256, DSMEM_MM>>>(adj, gBhi, gBlo, b1, gh);

    // Y2 = h1 @ W2, split+transpose
    sgemm_kernel<false, false><<<dim3(D2 / 64, NN / 64), 256>>>(gh, W2, nullptr, gy, NN, D2, D1);
    convT_kernel<<<dim3(NN / 32, 256 / 32), dim3(32, 8)>>>(gy);

    // h2 = relu(A @ Y2 + b2)   (overwrites g_h — safe, h1 fully consumed)
    bigmm_kernel<<<dim3(2, NN / BM), 256, DSMEM_MM>>>(adj, gBhi, gBlo, b2, gh);

    // Q head
    sgemm_kernel<true, true><<<dim3(QH / 64, NN / 64), 256>>>(gh, Wq1, bq1, gx, NN, QH, D2);
    qout_kernel<<<NN / 8, 256>>>(gx, Wq2, bq2, out);
}

// round 7
// speedup vs baseline: 2.0023x; 1.2447x over previous
#include <cuda_runtime.h>
#include <cuda_bf16.h>
#include <cstdint>

// Problem dims (fixed)
#define NN   8192
#define D0   128
#define D1   256
#define D2   256
#define QH   128
#define EPSV 1e-5f

// bigmm tiling: BM=64, BN=128, BK=32, 4 stages (swizzled, no padding), 2 CTAs/SM
#define BM       64
#define BNT      128
#define BKK      32
#define NIT      (NN / BKK)              // 256
#define SA_SZ    4096                    // 64 rows * 64B  (one A matrix)
#define SB_SZ    8192                    // 128 rows * 64B (one B matrix)
#define STAGE_SZ (2 * SA_SZ + 2 * SB_SZ) // 24576
#define NSTAGE   4
#define DSMEM_MM (NSTAGE * STAGE_SZ)     // 98304 -> 2 CTAs/SM

// ---------------- scratch ---------------------------------------------------
__device__ float g_x[NN * QH];           // Q-hidden
__device__ float g_h[NN * D2];           // hidden (h1 then h2)
__device__ float g_part[64 * 2 * D0];
__device__ float g_scale[D0];
__device__ float g_shift[D0];
__device__ __nv_bfloat16 g_Bhi[(size_t)D1 * NN];   // Y^T hi [256, 8192]
__device__ __nv_bfloat16 g_Blo[(size_t)D1 * NN];   // Y^T lo

// ---------------- PTX helpers (baseline ISA) --------------------------------
__device__ __forceinline__ uint32_t smem_u32(const void* p) {
    uint32_t a;
    asm("{ .reg .u64 t; cvta.to.shared.u64 t, %1; cvt.u32.u64 %0, t; }" : "=r"(a) : "l"(p));
    return a;
}
__device__ __forceinline__ void cp_async16(uint32_t dst, const void* src) {
    asm volatile("cp.async.cg.shared.global [%0], [%1], 16;" :: "r"(dst), "l"(src) : "memory");
}
__device__ __forceinline__ void ldsm4(uint32_t& r0, uint32_t& r1, uint32_t& r2, uint32_t& r3,
                                      uint32_t a) {
    asm volatile("ldmatrix.sync.aligned.m8n8.x4.shared.b16 {%0,%1,%2,%3}, [%4];"
                 : "=r"(r0), "=r"(r1), "=r"(r2), "=r"(r3) : "r"(a));
}
__device__ __forceinline__ void mma_bf16(float* c, const uint32_t* a, const uint32_t* b) {
    asm volatile("mma.sync.aligned.m16n8k16.row.col.f32.bf16.bf16.f32 "
                 "{%0,%1,%2,%3}, {%4,%5,%6,%7}, {%8,%9}, {%0,%1,%2,%3};"
                 : "+f"(c[0]), "+f"(c[1]), "+f"(c[2]), "+f"(c[3])
                 : "r"(a[0]), "r"(a[1]), "r"(a[2]), "r"(a[3]), "r"(b[0]), "r"(b[1]));
}
__device__ __forceinline__ uint32_t pack_bf16x2(__nv_bfloat16 a, __nv_bfloat16 b) {
    uint16_t ua = *(uint16_t*)&a, ub = *(uint16_t*)&b;
    return (uint32_t)ua | ((uint32_t)ub << 16);
}
// swizzled 16B-chunk offset within a tile of 64B rows
__device__ __forceinline__ uint32_t swz(uint32_t row, uint32_t chunk) {
    return row * 64u + ((chunk ^ ((row >> 1) & 3u)) << 4);
}

// ---------------- batchnorm stats -> scale/shift -----------------------------
__global__ void bn_partial_kernel(const float* __restrict__ state) {
    int c = threadIdx.x, b = blockIdx.x;
    int r0 = b * (NN / 64);
    float s = 0.f, s2 = 0.f;
    #pragma unroll 4
    for (int r = 0; r < NN / 64; ++r) {
        float v = state[(size_t)(r0 + r) * D0 + c];
        s += v; s2 += v * v;
    }
    g_part[b * 2 * D0 + c]      = s;
    g_part[b * 2 * D0 + D0 + c] = s2;
}
__global__ void bn_final_kernel(const float* __restrict__ gamma,
                                const float* __restrict__ beta) {
    int c = threadIdx.x;
    float s = 0.f, s2 = 0.f;
    #pragma unroll
    for (int b = 0; b < 64; ++b) {
        s  += g_part[b * 2 * D0 + c];
        s2 += g_part[b * 2 * D0 + D0 + c];
    }
    float mean = s * (1.0f / NN);
    float var  = s2 * (1.0f / NN) - mean * mean;
    float sc = rsqrtf(var + EPSV) * gamma[c];
    g_scale[c] = sc;
    g_shift[c] = beta[c] - mean * sc;
}

// ---------------- small SGEMM, optionally: fused BN on A, split-T output ----
// C = op(A[M,K] @ B[K,N]).  TOUT: write bf16 hi/lo transposed [N, NN] instead.
template<bool BIAS, bool RELU, bool DOBN, bool TOUT>
__global__ void __launch_bounds__(256)
sgemm_kernel(const float* __restrict__ A, const float* __restrict__ B,
             const float* __restrict__ bias, float* __restrict__ C,
             __nv_bfloat16* __restrict__ outHi, __nv_bfloat16* __restrict__ outLo,
             int M, int N, int K) {
    constexpr int TBM = 64, TBN = 64, TBK = 16, TM = 4, TN = 4;
    __shared__ float As[TBK][TBM];
    __shared__ float Bs[TBK][TBN];
    __shared__ uint32_t ts[TOUT ? 64 * 65 : 1];
    const int tid = threadIdx.x;
    const int tx = tid % (TBN / TN);
    const int ty = tid / (TBN / TN);
    const int rowBase = blockIdx.y * TBM;
    const int colBase = blockIdx.x * TBN;
    const int aRow = tid / (TBK / 4);
    const int aCol = (tid % (TBK / 4)) * 4;
    const int bRow = tid / (TBN / 4);
    const int bCol = (tid % (TBN / 4)) * 4;
    float acc[TM][TN] = {};
    for (int k0 = 0; k0 < K; k0 += TBK) {
        float4 av = *(const float4*)(A + (size_t)(rowBase + aRow) * K + k0 + aCol);
        if (DOBN) {
            float4 sc = *(const float4*)(g_scale + k0 + aCol);
            float4 sh = *(const float4*)(g_shift + k0 + aCol);
            av.x = fmaf(av.x, sc.x, sh.x);
            av.y = fmaf(av.y, sc.y, sh.y);
            av.z = fmaf(av.z, sc.z, sh.z);
            av.w = fmaf(av.w, sc.w, sh.w);
        }
        As[aCol + 0][aRow] = av.x; As[aCol + 1][aRow] = av.y;
        As[aCol + 2][aRow] = av.z; As[aCol + 3][aRow] = av.w;
        float4 bv = *(const float4*)(B + (size_t)(k0 + bRow) * N + colBase + bCol);
        *(float4*)&Bs[bRow][bCol] = bv;
        __syncthreads();
        #pragma unroll
        for (int k = 0; k < TBK; ++k) {
            float4 a4 = *(const float4*)&As[k][ty * TM];
            float4 b4 = *(const float4*)&Bs[k][tx * TN];
            float a[TM] = {a4.x, a4.y, a4.z, a4.w};
            float b[TN] = {b4.x, b4.y, b4.z, b4.w};
            #pragma unroll
            for (int i = 0; i < TM; ++i)
                #pragma unroll
                for (int j = 0; j < TN; ++j)
                    acc[i][j] = fmaf(a[i], b[j], acc[i][j]);
        }
        __syncthreads();
    }

    if (!TOUT) {
        #pragma unroll
        for (int i = 0; i < TM; ++i) {
            int r = rowBase + ty * TM + i;
            #pragma unroll
            for (int j = 0; j < TN; ++j) {
                int c = colBase + tx * TN + j;
                float v = acc[i][j];
                if (BIAS) v += bias[c];
                if (RELU) v = fmaxf(v, 0.f);
                C[(size_t)r * N + c] = v;
            }
        }
    } else {
        // split to bf16 hi/lo, transpose via smem, store [col][row]
        #pragma unroll
        for (int i = 0; i < TM; ++i)
            #pragma unroll
            for (int j = 0; j < TN; ++j) {
                int cl = tx * TN + j, rl = ty * TM + i;
                float v = acc[i][j];
                __nv_bfloat16 hi = __float2bfloat16(v);
                __nv_bfloat16 lo = __float2bfloat16(v - __bfloat162float(hi));
                ts[cl * 65 + rl] = pack_bf16x2(hi, lo);
            }
        __syncthreads();
        #pragma unroll
        for (int i = 0; i < 8; ++i) {
            int id = i * 256 + tid;
            int cl = id >> 5, rp = (id & 31) * 2;
            uint32_t v0 = ts[cl * 65 + rp], v1 = ts[cl * 65 + rp + 1];
            uint32_t hh = (v0 & 0xFFFFu) | (v1 << 16);
            uint32_t ll = (v0 >> 16) | (v1 & 0xFFFF0000u);
            size_t o = (size_t)(colBase + cl) * NN + rowBase + rp;
            *(uint32_t*)(outHi + o) = hh;
            *(uint32_t*)(outLo + o) = ll;
        }
    }
}

// ---------------- big GEMM: C = relu(A_fp32 @ B^T + bias) --------------------
// A fp32 [NN,NN] row-major, split bf16 hi/lo in-kernel.  B hi/lo [256,NN] K-major.
// Tile 64x128xK32, 8 warps, 4-stage swizzled pipeline, 2 CTAs/SM.
__global__ void __launch_bounds__(256, 2)
bigmm_kernel(const float* __restrict__ A,
             const __nv_bfloat16* __restrict__ Bhi, const __nv_bfloat16* __restrict__ Blo,
             const float* __restrict__ bias, float* __restrict__ C) {
    extern __shared__ char sm[];
    const uint32_t sbase = smem_u32(sm);
    const int tid = threadIdx.x;
    const int n0 = blockIdx.x * BNT;
    const int m0 = blockIdx.y * BM;
    const int lrow = tid >> 2, lchk = tid & 3;

    // ---- loaders ----
    const float* gA = A + (size_t)(m0 + lrow) * NN + lchk * 8;
    const __nv_bfloat16* gBh = Bhi + (size_t)(n0 + lrow) * NN + lchk * 8;
    const __nv_bfloat16* gBl = Blo + (size_t)(n0 + lrow) * NN + lchk * 8;
    const uint32_t swA  = swz(lrow, lchk);          // A row chunk target
    const uint32_t swB0 = swz(lrow, lchk);          // B rows 0..63
    const uint32_t swB1 = swz(lrow + 64, lchk);     // B rows 64..127

    float4 rA[2];
    auto LDG_A = [&](int j) {
        const float* p = gA + (size_t)j * BKK;
        rA[0] = *(const float4*)(p + 0);
        rA[1] = *(const float4*)(p + 4);
    };
    auto STS_A = [&](int s) {
        const float* f = (const float*)rA;
        uint32_t hbuf[4], lbuf[4];
        #pragma unroll
        for (int e = 0; e < 4; ++e) {
            float x0 = f[2 * e], x1 = f[2 * e + 1];
            __nv_bfloat16 h0 = __float2bfloat16(x0);
            __nv_bfloat16 h1 = __float2bfloat16(x1);
            __nv_bfloat16 l0 = __float2bfloat16(x0 - __bfloat162float(h0));
            __nv_bfloat16 l1 = __float2bfloat16(x1 - __bfloat162float(h1));
            hbuf[e] = pack_bf16x2(h0, h1);
            lbuf[e] = pack_bf16x2(l0, l1);
        }
        char* dh = sm + s * STAGE_SZ + swA;
        *(uint4*)(dh)         = *(uint4*)hbuf;
        *(uint4*)(dh + SA_SZ) = *(uint4*)lbuf;
    };
    auto CP_B = [&](int s, int j) {
        uint32_t sb = sbase + s * STAGE_SZ + 2 * SA_SZ;
        size_t k = (size_t)j * BKK;
        cp_async16(sb + swB0,         gBh + k);
        cp_async16(sb + swB0 + SB_SZ, gBl + k);
        cp_async16(sb + swB1,         gBh + k + (size_t)64 * NN);
        cp_async16(sb + swB1 + SB_SZ, gBl + k + (size_t)64 * NN);
        asm volatile("cp.async.commit_group;" ::: "memory");
    };

    // ---- compute mapping: 8 warps = 2(m) x 4(n), warp tile 32x32 ----
    const int wid = tid >> 5, lane = tid & 31;
    const int wm = wid & 1, wn = wid >> 1;
    const uint32_t rowA0 = wm * 32 + (lane & 15);
    const uint32_t ca    = lane >> 4;               // 0/1
    const uint32_t rowB0 = wn * 32 + ((lane >> 4) << 3) + (lane & 7);
    const uint32_t cb    = (lane >> 3) & 1;

    float acc[2][4][4];
    #pragma unroll
    for (int mt = 0; mt < 2; ++mt)
        #pragma unroll
        for (int nt = 0; nt < 4; ++nt)
            #pragma unroll
            for (int e = 0; e < 4; ++e) acc[mt][nt][e] = 0.f;

    // ---- prologue ----
    LDG_A(0); STS_A(0); CP_B(0, 0);
    LDG_A(1); STS_A(1); CP_B(1, 1);
    LDG_A(2); STS_A(2); CP_B(2, 2);
    LDG_A(3);

    for (int j = 0; j < NIT; ++j) {
        const int rem = NIT - 1 - j;
        if (rem >= 2)      { asm volatile("cp.async.wait_group 2;" ::: "memory"); }
        else if (rem == 1) { asm volatile("cp.async.wait_group 1;" ::: "memory"); }
        else               { asm volatile("cp.async.wait_group 0;" ::: "memory"); }
        __syncthreads();
        if (j + 3 < NIT) {
            const int ls = (j + 3) & (NSTAGE - 1);
            STS_A(ls);                 // rA holds data for iteration j+3
            CP_B(ls, j + 3);
        }
        if (j + 4 < NIT) LDG_A(j + 4);

        const uint32_t sb  = sbase + (j & (NSTAGE - 1)) * STAGE_SZ;
        const uint32_t sbB = sb + 2 * SA_SZ;
        #pragma unroll
        for (int kh = 0; kh < 2; ++kh) {
            uint32_t ah[2][4], al[2][4], bh[4][2], bl[4][2];
            #pragma unroll
            for (int mt = 0; mt < 2; ++mt) {
                uint32_t ad = sb + swz(rowA0 + mt * 16, kh * 2 + ca);
                ldsm4(ah[mt][0], ah[mt][1], ah[mt][2], ah[mt][3], ad);
                ldsm4(al[mt][0], al[mt][1], al[mt][2], al[mt][3], ad + SA_SZ);
            }
            #pragma unroll
            for (int p = 0; p < 2; ++p) {
                uint32_t bd = sbB + swz(rowB0 + p * 16, kh * 2 + cb);
                uint32_t r0, r1, r2, r3;
                ldsm4(r0, r1, r2, r3, bd);
                bh[2 * p][0] = r0; bh[2 * p][1] = r1;
                bh[2 * p + 1][0] = r2; bh[2 * p + 1][1] = r3;
                ldsm4(r0, r1, r2, r3, bd + SB_SZ);
                bl[2 * p][0] = r0; bl[2 * p][1] = r1;
                bl[2 * p + 1][0] = r2; bl[2 * p + 1][1] = r3;
            }
            #pragma unroll
            for (int mt = 0; mt < 2; ++mt)
                #pragma unroll
                for (int nt = 0; nt < 4; ++nt)
                    mma_bf16(acc[mt][nt], ah[mt], bh[nt]);
            #pragma unroll
            for (int mt = 0; mt < 2; ++mt)
                #pragma unroll
                for (int nt = 0; nt < 4; ++nt)
                    mma_bf16(acc[mt][nt], ah[mt], bl[nt]);
            #pragma unroll
            for (int mt = 0; mt < 2; ++mt)
                #pragma unroll
                for (int nt = 0; nt < 4; ++nt)
                    mma_bf16(acc[mt][nt], al[mt], bh[nt]);
        }
    }

    // ---- epilogue: bias + relu + store ----
    #pragma unroll
    for (int mt = 0; mt < 2; ++mt) {
        #pragma unroll
        for (int nt = 0; nt < 4; ++nt) {
            int r = m0 + wm * 32 + mt * 16 + (lane >> 2);
            int c = n0 + wn * 32 + nt * 8 + (lane & 3) * 2;
            float b0 = bias[c], b1 = bias[c + 1];
            float2 v0;
            v0.x = fmaxf(acc[mt][nt][0] + b0, 0.f);
            v0.y = fmaxf(acc[mt][nt][1] + b1, 0.f);
            *(float2*)(C + (size_t)r * 256 + c) = v0;
            float2 v1;
            v1.x = fmaxf(acc[mt][nt][2] + b0, 0.f);
            v1.y = fmaxf(acc[mt][nt][3] + b1, 0.f);
            *(float2*)(C + (size_t)(r + 8) * 256 + c) = v1;
        }
    }
}

// ---------------- final Q output --------------------------------------------
__global__ void qout_kernel(const float* __restrict__ T,
                            const float* __restrict__ Wq2,
                            const float* __restrict__ bq2,
                            float* __restrict__ out) {
    int warp = threadIdx.x >> 5;
    int lane = threadIdx.x & 31;
    int row  = blockIdx.x * 8 + warp;
    const float* t = T + (size_t)row * QH;
    float s = 0.f;
    #pragma unroll
    for (int k = lane; k < QH; k += 32) s += t[k] * Wq2[k];
    #pragma unroll
    for (int o = 16; o; o >>= 1) s += __shfl_xor_sync(0xffffffffu, s, o);
    if (lane == 0) out[row] = s + bq2[0];
}

// ---------------- launcher --------------------------------------------------
extern "C" void kernel_launch(void* const* d_in, const int* in_sizes, int n_in,
                              void* d_out, int out_size) {
    const float* state = (const float*)d_in[0];
    const float* adj   = (const float*)d_in[1];
    const float* gamma = (const float*)d_in[2];
    const float* beta  = (const float*)d_in[3];
    const float* W1    = (const float*)d_in[4];
    const float* b1    = (const float*)d_in[5];
    const float* W2    = (const float*)d_in[6];
    const float* b2    = (const float*)d_in[7];
    const float* Wq1   = (const float*)d_in[8];
    const float* bq1   = (const float*)d_in[9];
    const float* Wq2   = (const float*)d_in[10];
    const float* bq2   = (const float*)d_in[11];
    float* out = (float*)d_out;

    float *gx, *gh;
    cudaGetSymbolAddress((void**)&gx, g_x);
    cudaGetSymbolAddress((void**)&gh, g_h);
    __nv_bfloat16 *gBhi, *gBlo;
    cudaGetSymbolAddress((void**)&gBhi, g_Bhi);
    cudaGetSymbolAddress((void**)&gBlo, g_Blo);

    cudaFuncSetAttribute(bigmm_kernel, cudaFuncAttributeMaxDynamicSharedMemorySize, DSMEM_MM);

    // BatchNorm stats -> scale/shift
    bn_partial_kernel<<<64, D0>>>(state);
    bn_final_kernel<<<1, D0>>>(gamma, beta);

    // Y1^T(hi/lo) = split_T(bn(state) @ W1)
    sgemm_kernel<false, false, true, true>
        <<<dim3(D1 / 64, NN / 64), 256>>>(state, W1, nullptr, nullptr, gBhi, gBlo, NN, D1, D0);

    // h1 = relu(A @ Y1 + b1)
    bigmm_kernel<<<dim3(2, NN / BM), 256, DSMEM_MM>>>(adj, gBhi, gBlo, b1, gh);

    // Y2^T(hi/lo) = split_T(h1 @ W2)
    sgemm_kernel<false, false, false, true>
        <<<dim3(D2 / 64, NN / 64), 256>>>(gh, W2, nullptr, nullptr, gBhi, gBlo, NN, D2, D1);

    // h2 = relu(A @ Y2 + b2)
    bigmm_kernel<<<dim3(2, NN / BM), 256, DSMEM_MM>>>(adj, gBhi, gBlo, b2, gh);

    // Q head
    sgemm_kernel<true, true, false, false>
        <<<dim3(QH / 64, NN / 64), 256>>>(gh, Wq1, bq1, gx, nullptr, nullptr, NN, QH, D2);
    qout_kernel<<<NN / 8, 256>>>(gx, Wq2, bq2, out);
}

// round 10
// speedup vs baseline: 2.0127x; 1.0052x over previous
#include <cuda_runtime.h>
#include <cuda_bf16.h>
#include <cstdint>

// Problem dims (fixed)
#define NN   8192
#define D0   128
#define D1   256
#define D2   256
#define QH   128
#define EPSV 1e-5f

// bigmm tiling: BM=64, BN=128, BK=32, 4 stages (swizzled), 2 CTAs/SM
#define BM       64
#define BNT      128
#define BKK      32
#define NIT      (NN / BKK)              // 256
#define SA_SZ    4096                    // 64 rows * 64B  (one A matrix)
#define SB_SZ    8192                    // 128 rows * 64B (one B matrix)
#define STAGE_SZ (2 * SA_SZ + 2 * SB_SZ) // 24576
#define NSTAGE   4
#define DSMEM_MM (NSTAGE * STAGE_SZ)     // 98304 -> 2 CTAs/SM

// ---------------- scratch ---------------------------------------------------
__device__ float g_x[NN * QH];           // Q-hidden
__device__ float g_h[NN * D2];           // hidden (h1 then h2)
__device__ float g_part[64 * 2 * D0];
__device__ float g_scale[D0];
__device__ float g_shift[D0];
__device__ __nv_bfloat16 g_Bhi[(size_t)D1 * NN];   // Y^T hi [256, 8192]
__device__ __nv_bfloat16 g_Blo[(size_t)D1 * NN];   // Y^T lo

// ---------------- PTX helpers (baseline ISA) --------------------------------
__device__ __forceinline__ uint32_t smem_u32(const void* p) {
    uint32_t a;
    asm("{ .reg .u64 t; cvta.to.shared.u64 t, %1; cvt.u32.u64 %0, t; }" : "=r"(a) : "l"(p));
    return a;
}
__device__ __forceinline__ void cp_async16(uint32_t dst, const void* src) {
    asm volatile("cp.async.cg.shared.global [%0], [%1], 16;" :: "r"(dst), "l"(src) : "memory");
}
__device__ __forceinline__ void ldsm4(uint32_t& r0, uint32_t& r1, uint32_t& r2, uint32_t& r3,
                                      uint32_t a) {
    asm volatile("ldmatrix.sync.aligned.m8n8.x4.shared.b16 {%0,%1,%2,%3}, [%4];"
                 : "=r"(r0), "=r"(r1), "=r"(r2), "=r"(r3) : "r"(a));
}
__device__ __forceinline__ void mma_bf16(float* c, const uint32_t* a, const uint32_t* b) {
    asm volatile("mma.sync.aligned.m16n8k16.row.col.f32.bf16.bf16.f32 "
                 "{%0,%1,%2,%3}, {%4,%5,%6,%7}, {%8,%9}, {%0,%1,%2,%3};"
                 : "+f"(c[0]), "+f"(c[1]), "+f"(c[2]), "+f"(c[3])
                 : "r"(a[0]), "r"(a[1]), "r"(a[2]), "r"(a[3]), "r"(b[0]), "r"(b[1]));
}
__device__ __forceinline__ uint32_t pack_bf16x2(__nv_bfloat16 a, __nv_bfloat16 b) {
    uint16_t ua = *(uint16_t*)&a, ub = *(uint16_t*)&b;
    return (uint32_t)ua | ((uint32_t)ub << 16);
}
// swizzled 16B-chunk offset within a tile of 64B rows
__device__ __forceinline__ uint32_t swz(uint32_t row, uint32_t chunk) {
    return row * 64u + ((chunk ^ ((row >> 1) & 3u)) << 4);
}

// ---------------- batchnorm stats -> scale/shift -----------------------------
__global__ void bn_partial_kernel(const float* __restrict__ state) {
    int c = threadIdx.x, b = blockIdx.x;
    int r0 = b * (NN / 64);
    float s = 0.f, s2 = 0.f;
    #pragma unroll 4
    for (int r = 0; r < NN / 64; ++r) {
        float v = state[(size_t)(r0 + r) * D0 + c];
        s += v; s2 += v * v;
    }
    g_part[b * 2 * D0 + c]      = s;
    g_part[b * 2 * D0 + D0 + c] = s2;
}
__global__ void bn_final_kernel(const float* __restrict__ gamma,
                                const float* __restrict__ beta) {
    int c = threadIdx.x;
    float s = 0.f, s2 = 0.f;
    #pragma unroll
    for (int b = 0; b < 64; ++b) {
        s  += g_part[b * 2 * D0 + c];
        s2 += g_part[b * 2 * D0 + D0 + c];
    }
    float mean = s * (1.0f / NN);
    float var  = s2 * (1.0f / NN) - mean * mean;
    float sc = rsqrtf(var + EPSV) * gamma[c];
    g_scale[c] = sc;
    g_shift[c] = beta[c] - mean * sc;
}

// ---------------- small SGEMM, optionally: fused BN on A, split-T output ----
template<bool BIAS, bool RELU, bool DOBN, bool TOUT>
__global__ void __launch_bounds__(256)
sgemm_kernel(const float* __restrict__ A, const float* __restrict__ B,
             const float* __restrict__ bias, float* __restrict__ C,
             __nv_bfloat16* __restrict__ outHi, __nv_bfloat16* __restrict__ outLo,
             int M, int N, int K) {
    constexpr int TBM = 64, TBN = 64, TBK = 16, TM = 4, TN = 4;
    __shared__ float As[TBK][TBM];
    __shared__ float Bs[TBK][TBN];
    __shared__ uint32_t ts[TOUT ? 64 * 65 : 1];
    const int tid = threadIdx.x;
    const int tx = tid % (TBN / TN);
    const int ty = tid / (TBN / TN);
    const int rowBase = blockIdx.y * TBM;
    const int colBase = blockIdx.x * TBN;
    const int aRow = tid / (TBK / 4);
    const int aCol = (tid % (TBK / 4)) * 4;
    const int bRow = tid / (TBN / 4);
    const int bCol = (tid % (TBN / 4)) * 4;
    float acc[TM][TN] = {};
    for (int k0 = 0; k0 < K; k0 += TBK) {
        float4 av = *(const float4*)(A + (size_t)(rowBase + aRow) * K + k0 + aCol);
        if (DOBN) {
            float4 sc = *(const float4*)(g_scale + k0 + aCol);
            float4 sh = *(const float4*)(g_shift + k0 + aCol);
            av.x = fmaf(av.x, sc.x, sh.x);
            av.y = fmaf(av.y, sc.y, sh.y);
            av.z = fmaf(av.z, sc.z, sh.z);
            av.w = fmaf(av.w, sc.w, sh.w);
        }
        As[aCol + 0][aRow] = av.x; As[aCol + 1][aRow] = av.y;
        As[aCol + 2][aRow] = av.z; As[aCol + 3][aRow] = av.w;
        float4 bv = *(const float4*)(B + (size_t)(k0 + bRow) * N + colBase + bCol);
        *(float4*)&Bs[bRow][bCol] = bv;
        __syncthreads();
        #pragma unroll
        for (int k = 0; k < TBK; ++k) {
            float4 a4 = *(const float4*)&As[k][ty * TM];
            float4 b4 = *(const float4*)&Bs[k][tx * TN];
            float a[TM] = {a4.x, a4.y, a4.z, a4.w};
            float b[TN] = {b4.x, b4.y, b4.z, b4.w};
            #pragma unroll
            for (int i = 0; i < TM; ++i)
                #pragma unroll
                for (int j = 0; j < TN; ++j)
                    acc[i][j] = fmaf(a[i], b[j], acc[i][j]);
        }
        __syncthreads();
    }

    if (!TOUT) {
        #pragma unroll
        for (int i = 0; i < TM; ++i) {
            int r = rowBase + ty * TM + i;
            #pragma unroll
            for (int j = 0; j < TN; ++j) {
                int c = colBase + tx * TN + j;
                float v = acc[i][j];
                if (BIAS) v += bias[c];
                if (RELU) v = fmaxf(v, 0.f);
                C[(size_t)r * N + c] = v;
            }
        }
    } else {
        #pragma unroll
        for (int i = 0; i < TM; ++i)
            #pragma unroll
            for (int j = 0; j < TN; ++j) {
                int cl = tx * TN + j, rl = ty * TM + i;
                float v = acc[i][j];
                __nv_bfloat16 hi = __float2bfloat16(v);
                __nv_bfloat16 lo = __float2bfloat16(v - __bfloat162float(hi));
                ts[cl * 65 + rl] = pack_bf16x2(hi, lo);
            }
        __syncthreads();
        #pragma unroll
        for (int i = 0; i < 8; ++i) {
            int id = i * 256 + tid;
            int cl = id >> 5, rp = (id & 31) * 2;
            uint32_t v0 = ts[cl * 65 + rp], v1 = ts[cl * 65 + rp + 1];
            uint32_t hh = (v0 & 0xFFFFu) | (v1 << 16);
            uint32_t ll = (v0 >> 16) | (v1 & 0xFFFF0000u);
            size_t o = (size_t)(colBase + cl) * NN + rowBase + rp;
            *(uint32_t*)(outHi + o) = hh;
            *(uint32_t*)(outLo + o) = ll;
        }
    }
}

// ---------------- big GEMM: C = relu(A_fp32 @ B^T + bias) --------------------
// A fp32 [NN,NN] row-major, split bf16 hi/lo in-kernel.  B hi/lo [256,NN] K-major.
// Tile 64x128xK32, 8 warps, 4-stage swizzled pipeline, 2 CTAs/SM.
// Inner loop software-pipelined: kh=1 hi-fragments prefetched during kh=0 mma,
// lo-fragments reload into dead registers mid-stream.
__global__ void __launch_bounds__(256, 2)
bigmm_kernel(const float* __restrict__ A,
             const __nv_bfloat16* __restrict__ Bhi, const __nv_bfloat16* __restrict__ Blo,
             const float* __restrict__ bias, float* __restrict__ C) {
    extern __shared__ char sm[];
    const uint32_t sbase = smem_u32(sm);
    const int tid = threadIdx.x;
    const int n0 = blockIdx.x * BNT;
    const int m0 = blockIdx.y * BM;
    const int lrow = tid >> 2, lchk = tid & 3;

    // ---- loaders ----
    const float* gA = A + (size_t)(m0 + lrow) * NN + lchk * 8;
    const __nv_bfloat16* gBh = Bhi + (size_t)(n0 + lrow) * NN + lchk * 8;
    const __nv_bfloat16* gBl = Blo + (size_t)(n0 + lrow) * NN + lchk * 8;
    const uint32_t swA  = swz(lrow, lchk);
    const uint32_t swB0 = swz(lrow, lchk);
    const uint32_t swB1 = swz(lrow + 64, lchk);

    float4 rA[2];
    auto LDG_A = [&](int j) {
        const float* p = gA + (size_t)j * BKK;
        rA[0] = *(const float4*)(p + 0);
        rA[1] = *(const float4*)(p + 4);
    };
    auto STS_A = [&](int s) {
        const float* f = (const float*)rA;
        uint32_t hbuf[4], lbuf[4];
        #pragma unroll
        for (int e = 0; e < 4; ++e) {
            float x0 = f[2 * e], x1 = f[2 * e + 1];
            __nv_bfloat16 h0 = __float2bfloat16(x0);
            __nv_bfloat16 h1 = __float2bfloat16(x1);
            __nv_bfloat16 l0 = __float2bfloat16(x0 - __bfloat162float(h0));
            __nv_bfloat16 l1 = __float2bfloat16(x1 - __bfloat162float(h1));
            hbuf[e] = pack_bf16x2(h0, h1);
            lbuf[e] = pack_bf16x2(l0, l1);
        }
        char* dh = sm + s * STAGE_SZ + swA;
        *(uint4*)(dh)         = *(uint4*)hbuf;
        *(uint4*)(dh + SA_SZ) = *(uint4*)lbuf;
    };
    auto CP_B = [&](int s, int j) {
        uint32_t sb = sbase + s * STAGE_SZ + 2 * SA_SZ;
        size_t k = (size_t)j * BKK;
        cp_async16(sb + swB0,         gBh + k);
        cp_async16(sb + swB0 + SB_SZ, gBl + k);
        cp_async16(sb + swB1,         gBh + k + (size_t)64 * NN);
        cp_async16(sb + swB1 + SB_SZ, gBl + k + (size_t)64 * NN);
        asm volatile("cp.async.commit_group;" ::: "memory");
    };

    // ---- compute mapping: 8 warps = 2(m) x 4(n), warp tile 32x32 ----
    const int wid = tid >> 5, lane = tid & 31;
    const int wm = wid & 1, wn = wid >> 1;
    const uint32_t rowA0 = wm * 32 + (lane & 15);
    const uint32_t ca    = lane >> 4;               // 0/1
    const uint32_t rowB0 = wn * 32 + ((lane >> 4) << 3) + (lane & 7);
    const uint32_t cb    = (lane >> 3) & 1;

    float acc[2][4][4];
    #pragma unroll
    for (int mt = 0; mt < 2; ++mt)
        #pragma unroll
        for (int nt = 0; nt < 4; ++nt)
            #pragma unroll
            for (int e = 0; e < 4; ++e) acc[mt][nt][e] = 0.f;

    // ---- prologue ----
    LDG_A(0); STS_A(0); CP_B(0, 0);
    LDG_A(1); STS_A(1); CP_B(1, 1);
    LDG_A(2); STS_A(2); CP_B(2, 2);
    LDG_A(3);

    for (int j = 0; j < NIT; ++j) {
        const int rem = NIT - 1 - j;
        if (rem >= 2)      { asm volatile("cp.async.wait_group 2;" ::: "memory"); }
        else if (rem == 1) { asm volatile("cp.async.wait_group 1;" ::: "memory"); }
        else               { asm volatile("cp.async.wait_group 0;" ::: "memory"); }
        __syncthreads();
        if (j + 3 < NIT) {
            const int ls = (j + 3) & (NSTAGE - 1);
            STS_A(ls);
            CP_B(ls, j + 3);
        }
        if (j + 4 < NIT) LDG_A(j + 4);

        const uint32_t sb  = sbase + (j & (NSTAGE - 1)) * STAGE_SZ;
        const uint32_t sbB = sb + 2 * SA_SZ;

        // ---- software-pipelined fragment schedule over kh = 0,1 ----
        uint32_t ah[2][4], al[2][4], bh[4][2], bl[4][2];  // current-kh fragments
        uint32_t ah2[2][4], bh2[4][2];                    // next-kh hi prefetch

        // kh=0 fragments
        #pragma unroll
        for (int mt = 0; mt < 2; ++mt) {
            uint32_t ad = sb + swz(rowA0 + mt * 16, ca);
            ldsm4(ah[mt][0], ah[mt][1], ah[mt][2], ah[mt][3], ad);
            ldsm4(al[mt][0], al[mt][1], al[mt][2], al[mt][3], ad + SA_SZ);
        }
        #pragma unroll
        for (int p = 0; p < 2; ++p) {
            uint32_t bd = sbB + swz(rowB0 + p * 16, cb);
            uint32_t r0, r1, r2, r3;
            ldsm4(r0, r1, r2, r3, bd);
            bh[2 * p][0] = r0; bh[2 * p][1] = r1;
            bh[2 * p + 1][0] = r2; bh[2 * p + 1][1] = r3;
            ldsm4(r0, r1, r2, r3, bd + SB_SZ);
            bl[2 * p][0] = r0; bl[2 * p][1] = r1;
            bl[2 * p + 1][0] = r2; bl[2 * p + 1][1] = r3;
        }
        // kh=1 hi prefetch
        #pragma unroll
        for (int mt = 0; mt < 2; ++mt)
            ldsm4(ah2[mt][0], ah2[mt][1], ah2[mt][2], ah2[mt][3],
                  sb + swz(rowA0 + mt * 16, 2 + ca));
        #pragma unroll
        for (int p = 0; p < 2; ++p) {
            uint32_t r0, r1, r2, r3;
            ldsm4(r0, r1, r2, r3, sbB + swz(rowB0 + p * 16, 2 + cb));
            bh2[2 * p][0] = r0; bh2[2 * p][1] = r1;
            bh2[2 * p + 1][0] = r2; bh2[2 * p + 1][1] = r3;
        }

        // kh=0: term1 hi*hi, term3 lo*hi (al dies), then reload al for kh=1
        #pragma unroll
        for (int mt = 0; mt < 2; ++mt)
            #pragma unroll
            for (int nt = 0; nt < 4; ++nt)
                mma_bf16(acc[mt][nt], ah[mt], bh[nt]);
        #pragma unroll
        for (int mt = 0; mt < 2; ++mt)
            #pragma unroll
            for (int nt = 0; nt < 4; ++nt)
                mma_bf16(acc[mt][nt], al[mt], bh[nt]);
        #pragma unroll
        for (int mt = 0; mt < 2; ++mt)
            ldsm4(al[mt][0], al[mt][1], al[mt][2], al[mt][3],
                  sb + SA_SZ + swz(rowA0 + mt * 16, 2 + ca));
        // kh=0: term2 hi*lo (bl dies), then reload bl for kh=1
        #pragma unroll
        for (int mt = 0; mt < 2; ++mt)
            #pragma unroll
            for (int nt = 0; nt < 4; ++nt)
                mma_bf16(acc[mt][nt], ah[mt], bl[nt]);
        #pragma unroll
        for (int p = 0; p < 2; ++p) {
            uint32_t r0, r1, r2, r3;
            ldsm4(r0, r1, r2, r3, sbB + SB_SZ + swz(rowB0 + p * 16, 2 + cb));
            bl[2 * p][0] = r0; bl[2 * p][1] = r1;
            bl[2 * p + 1][0] = r2; bl[2 * p + 1][1] = r3;
        }

        // kh=1: all three terms from prefetched/reloaded fragments
        #pragma unroll
        for (int mt = 0; mt < 2; ++mt)
            #pragma unroll
            for (int nt = 0; nt < 4; ++nt)
                mma_bf16(acc[mt][nt], ah2[mt], bh2[nt]);
        #pragma unroll
        for (int mt = 0; mt < 2; ++mt)
            #pragma unroll
            for (int nt = 0; nt < 4; ++nt)
                mma_bf16(acc[mt][nt], al[mt], bh2[nt]);
        #pragma unroll
        for (int mt = 0; mt < 2; ++mt)
            #pragma unroll
            for (int nt = 0; nt < 4; ++nt)
                mma_bf16(acc[mt][nt], ah2[mt], bl[nt]);
    }

    // ---- epilogue: bias + relu + store ----
    #pragma unroll
    for (int mt = 0; mt < 2; ++mt) {
        #pragma unroll
        for (int nt = 0; nt < 4; ++nt) {
            int r = m0 + wm * 32 + mt * 16 + (lane >> 2);
            int c = n0 + wn * 32 + nt * 8 + (lane & 3) * 2;
            float b0 = bias[c], b1 = bias[c + 1];
            float2 v0;
            v0.x = fmaxf(acc[mt][nt][0] + b0, 0.f);
            v0.y = fmaxf(acc[mt][nt][1] + b1, 0.f);
            *(float2*)(C + (size_t)r * 256 + c) = v0;
            float2 v1;
            v1.x = fmaxf(acc[mt][nt][2] + b0, 0.f);
            v1.y = fmaxf(acc[mt][nt][3] + b1, 0.f);
            *(float2*)(C + (size_t)(r + 8) * 256 + c) = v1;
        }
    }
}

// ---------------- final Q output --------------------------------------------
__global__ void qout_kernel(const float* __restrict__ T,
                            const float* __restrict__ Wq2,
                            const float* __restrict__ bq2,
                            float* __restrict__ out) {
    int warp = threadIdx.x >> 5;
    int lane = threadIdx.x & 31;
    int row  = blockIdx.x * 8 + warp;
    const float* t = T + (size_t)row * QH;
    float s = 0.f;
    #pragma unroll
    for (int k = lane; k < QH; k += 32) s += t[k] * Wq2[k];
    #pragma unroll
    for (int o = 16; o; o >>= 1) s += __shfl_xor_sync(0xffffffffu, s, o);
    if (lane == 0) out[row] = s + bq2[0];
}

// ---------------- launcher --------------------------------------------------
extern "C" void kernel_launch(void* const* d_in, const int* in_sizes, int n_in,
                              void* d_out, int out_size) {
    const float* state = (const float*)d_in[0];
    const float* adj   = (const float*)d_in[1];
    const float* gamma = (const float*)d_in[2];
    const float* beta  = (const float*)d_in[3];
    const float* W1    = (const float*)d_in[4];
    const float* b1    = (const float*)d_in[5];
    const float* W2    = (const float*)d_in[6];
    const float* b2    = (const float*)d_in[7];
    const float* Wq1   = (const float*)d_in[8];
    const float* bq1   = (const float*)d_in[9];
    const float* Wq2   = (const float*)d_in[10];
    const float* bq2   = (const float*)d_in[11];
    float* out = (float*)d_out;

    float *gx, *gh;
    cudaGetSymbolAddress((void**)&gx, g_x);
    cudaGetSymbolAddress((void**)&gh, g_h);
    __nv_bfloat16 *gBhi, *gBlo;
    cudaGetSymbolAddress((void**)&gBhi, g_Bhi);
    cudaGetSymbolAddress((void**)&gBlo, g_Blo);

    cudaFuncSetAttribute(bigmm_kernel, cudaFuncAttributeMaxDynamicSharedMemorySize, DSMEM_MM);

    // BatchNorm stats -> scale/shift
    bn_partial_kernel<<<64, D0>>>(state);
    bn_final_kernel<<<1, D0>>>(gamma, beta);

    // Y1^T(hi/lo) = split_T(bn(state) @ W1)
    sgemm_kernel<false, false, true, true>
        <<<dim3(D1 / 64, NN / 64), 256>>>(state, W1, nullptr, nullptr, gBhi, gBlo, NN, D1, D0);

    // h1 = relu(A @ Y1 + b1)
    bigmm_kernel<<<dim3(2, NN / BM), 256, DSMEM_MM>>>(adj, gBhi, gBlo, b1, gh);

    // Y2^T(hi/lo) = split_T(h1 @ W2)
    sgemm_kernel<false, false, false, true>
        <<<dim3(D2 / 64, NN / 64), 256>>>(gh, W2, nullptr, nullptr, gBhi, gBlo, NN, D2, D1);

    // h2 = relu(A @ Y2 + b2)
    bigmm_kernel<<<dim3(2, NN / BM), 256, DSMEM_MM>>>(adj, gBhi, gBlo, b2, gh);

    // Q head
    sgemm_kernel<true, true, false, false>
        <<<dim3(QH / 64, NN / 64), 256>>>(gh, Wq1, bq1, gx, nullptr, nullptr, NN, QH, D2);
    qout_kernel<<<NN / 8, 256>>>(gx, Wq2, bq2, out);
}